// round 6
// baseline (speedup 1.0000x reference)
#include <cuda_runtime.h>

#define HID 50
#define GP  224      // gates padded: 4 types * 56 j-slots
#define K4N 13       // k padded 50->52, 4 per float4
#define BT  8        // batch rows per CTA
#define NTHREADS 256 // 8 warps
#define GSTRIDE 225  // gates row stride (floats), odd
#define HPK4 (K4N * BT)   // h buffer float4 count

typedef unsigned long long u64;

// Packed fp32x2 FMA (Blackwell), exact fp32 semantics per lane.
__device__ __forceinline__ void ffma2(u64& d, u64 a, u64 b) {
    asm("fma.rn.f32x2 %0, %1, %2, %3;" : "=l"(d) : "l"(a), "l"(b), "l"(d));
}
__device__ __forceinline__ float f2lo(u64 a) { return __uint_as_float((unsigned)a); }
__device__ __forceinline__ float f2hi(u64 a) { return __uint_as_float((unsigned)(a >> 32)); }

__device__ __forceinline__ float sigmoidf_(float x) {
    float e = __expf(-x);
    return __fdividef(1.f, 1.f + e);
}
__device__ __forceinline__ float tanhf_(float x) {
    float e = __expf(2.f * x);
    return 1.f - __fdividef(2.f, e + 1.f);
}

__global__ void __launch_bounds__(NTHREADS, 2)
seq2seq_kernel(const float* __restrict__ source,
               const float* __restrict__ eWih, const float* __restrict__ eWhh,
               const float* __restrict__ eBih, const float* __restrict__ eBhh,
               const float* __restrict__ dWih, const float* __restrict__ dWhh,
               const float* __restrict__ dBih, const float* __restrict__ dBhh,
               const float* __restrict__ fcW,  const float* __restrict__ fcB,
               float* __restrict__ out, int S, int T)
{
    extern __shared__ char smem_raw[];
    float4* wbuf  = (float4*)smem_raw;          // [K4N][GP] one phase at a time
    float4* hpk   = wbuf + K4N * GP;            // [K4N][BT] packed h
    float*  gates = (float*)(hpk + HPK4);       // [BT][GSTRIDE]
    float*  xdec  = gates + BT * GSTRIDE;       // [BT]
    float*  fcw   = xdec + BT;                  // [HID]
    float*  fcb   = fcw + HID;                  // [2]
    float*  srcs  = fcb + 2;                    // [BT][S]

    const int tid  = threadIdx.x;
    const int lane = tid & 31;
    const int wrp  = tid >> 5;                  // [0,8)
    const int b0g  = blockIdx.x * BT;

    // GEMM tile: thread = (1 batch row, 7 gates). warp w owns gate-groups {4w..4w+3}
    const int bgrp  = lane >> 2;                // [0,8): batch row
    const int ggl   = lane & 3;
    const int gg    = wrp * 4 + ggl;            // [0,32)
    const int gbase = gg * 7;                   // [0,224)

    // weight stager (used for both phases)
    auto stage_w = [&](const float* Whh) {
        for (int idx = tid; idx < K4N * GP; idx += NTHREADS) {
            int k4 = idx / GP, g = idx % GP;
            int ty = g / 56, j = g % 56;
            float4 v = make_float4(0.f, 0.f, 0.f, 0.f);
            if (j < HID) {
                int row = ty * HID + j;
                #pragma unroll
                for (int c = 0; c < 4; c++) {
                    int k = 4 * k4 + c;
                    if (k < HID) ((float*)&v)[c] = Whh[row * HID + k];
                }
            }
            wbuf[idx] = v;
        }
    };

    stage_w(eWhh);
    for (int i = tid; i < HPK4; i += NTHREADS) hpk[i] = make_float4(0.f, 0.f, 0.f, 0.f);
    if (tid < BT)  xdec[tid] = 0.f;
    if (tid < HID) fcw[tid] = fcW[tid];
    if (tid == 0)  fcb[0] = fcB[0];
    for (int bl = 0; bl < BT; bl++)
        for (int t = tid; t < S; t += NTHREADS)
            srcs[bl * S + t] = source[(size_t)(b0g + bl) * S + t];

    // per-thread constants
    float biasr[7], wihr[7];
    auto stage_c = [&](const float* Wih, const float* Bih, const float* Bhh) {
        #pragma unroll
        for (int i = 0; i < 7; i++) {
            int g = gbase + i, ty = g / 56, j = g % 56;
            if (j < HID) { int r = ty * HID + j; biasr[i] = Bih[r] + Bhh[r]; wihr[i] = Wih[r]; }
            else         { biasr[i] = 0.f; wihr[i] = 0.f; }
        }
    };
    stage_c(eWih, eBih, eBhh);

    // update mapping: cell0 = (b = tid>>5, j = lane) covers j<32;
    // cell1 (tid<144): b = tid/18, j = 32 + tid%18
    const int bu0 = tid >> 5, ju0 = lane;
    const int bu1 = tid / 18, ju1 = 32 + tid % 18;
    const bool has1 = tid < BT * (HID - 32);    // 144
    float c0 = 0.f, c1 = 0.f;
    __syncthreads();

    const ulonglong2* w2 = (const ulonglong2*)wbuf;
    const ulonglong2* h2 = (const ulonglong2*)hpk;

    auto gemm = [&](float xv) {
        u64 acc[7];
        #pragma unroll
        for (int i = 0; i < 7; i++)
            acc[i] = (u64)__float_as_uint(fmaf(xv, wihr[i], biasr[i]));
        #pragma unroll
        for (int k4 = 0; k4 < K4N; k4++) {
            ulonglong2 hv = h2[k4 * BT + bgrp];            // 8 distinct 16B = 1 wf
            #pragma unroll
            for (int i = 0; i < 7; i++) {
                ulonglong2 wv = w2[k4 * GP + gbase + i];   // 4 distinct 16B = 1 wf
                ffma2(acc[i], wv.x, hv.x);
                ffma2(acc[i], wv.y, hv.y);
            }
        }
        #pragma unroll
        for (int i = 0; i < 7; i++) {
            u64 a = acc[i];
            gates[bgrp * GSTRIDE + gbase + i] = f2lo(a) + f2hi(a);
        }
    };

    auto upd_one = [&](int b, int j, float& c) {
        float gi  = gates[b * GSTRIDE + j];
        float gf  = gates[b * GSTRIDE + 56 + j];
        float gg_ = gates[b * GSTRIDE + 112 + j];
        float go  = gates[b * GSTRIDE + 168 + j];
        float iv = sigmoidf_(gi);
        float fv = sigmoidf_(gf);
        float gv = tanhf_(gg_);
        float ov = sigmoidf_(go);
        c = fmaf(fv, c, iv * gv);
        float h = ov * tanhf_(c);
        ((float*)hpk)[(j >> 2) * (BT * 4) + b * 4 + (j & 3)] = h;
    };

    // ================= encoder =================
    for (int t = 0; t < S; t++) {
        gemm(srcs[bgrp * S + t]);
        __syncthreads();
        upd_one(bu0, ju0, c0);
        if (has1) upd_one(bu1, ju1, c1);
        __syncthreads();
    }

    // ================= swap to decoder weights =================
    stage_w(dWhh);
    stage_c(dWih, dBih, dBhh);
    __syncthreads();

    // ================= decoder =================
    for (int t = 0; t < T; t++) {
        gemm(xdec[bgrp]);
        __syncthreads();
        upd_one(bu0, ju0, c0);
        if (has1) upd_one(bu1, ju1, c1);
        __syncthreads();

        if (wrp == 0) {   // fc: lane = (bfc in [0,8), hhf in [0,4)); 13 j each
            const int bfc = lane & 7;
            const int hhf = lane >> 3;
            const float* hf = (const float*)hpk;
            float s = 0.f;
            #pragma unroll
            for (int jj = 0; jj < 13; jj++) {
                int jq = hhf * 13 + jj;
                if (jq < HID)
                    s = fmaf(hf[(jq >> 2) * (BT * 4) + bfc * 4 + (jq & 3)], fcw[jq], s);
            }
            s += __shfl_xor_sync(0xffffffffu, s, 8);
            s += __shfl_xor_sync(0xffffffffu, s, 16);
            if (hhf == 0) {
                float y = s + fcb[0];
                xdec[bfc] = y;
                out[(size_t)(b0g + bfc) * T + t] = y;
            }
        }
        __syncthreads();
    }
}

extern "C" void kernel_launch(void* const* d_in, const int* in_sizes, int n_in,
                              void* d_out, int out_size)
{
    const float* source = (const float*)d_in[0];
    const float* eWih = (const float*)d_in[1];
    const float* eWhh = (const float*)d_in[2];
    const float* eBih = (const float*)d_in[3];
    const float* eBhh = (const float*)d_in[4];
    const float* dWih = (const float*)d_in[5];
    const float* dWhh = (const float*)d_in[6];
    const float* dBih = (const float*)d_in[7];
    const float* dBhh = (const float*)d_in[8];
    const float* fcW  = (const float*)d_in[9];
    const float* fcB  = (const float*)d_in[10];
    float* out = (float*)d_out;

    const int B = 2048;
    const int S = in_sizes[0] / B;   // 512
    const int T = out_size   / B;    // 256

    size_t sm = sizeof(float4) * (size_t)(K4N * GP + HPK4)
              + sizeof(float)  * (size_t)(BT * GSTRIDE + BT + HID + 2)
              + sizeof(float)  * (size_t)BT * S;

    cudaFuncSetAttribute(seq2seq_kernel, cudaFuncAttributeMaxDynamicSharedMemorySize, (int)sm);
    seq2seq_kernel<<<B / BT, NTHREADS, sm>>>(source, eWih, eWhh, eBih, eBhh,
                                             dWih, dWhh, dBih, dBhh, fcW, fcB,
                                             out, S, T);
}

// round 7
// speedup vs baseline: 1.2507x; 1.2507x over previous
#include <cuda_runtime.h>

#define HID 50
#define JP  64          // padded hidden units -> 16 warps of 4 j each
#define K4N 13          // k padded 50->52, 4 per float4
#define BT  16          // batch rows per CTA
#define NTHREADS 512    // 16 warps, 4 per SMSP
#define HBUF_F4 (K4N * BT)   // 208 float4 per h buffer

typedef unsigned long long u64;

// Packed fp32x2 FMA (Blackwell), exact fp32 semantics per lane.
__device__ __forceinline__ void ffma2(u64& d, u64 a, u64 b) {
    asm("fma.rn.f32x2 %0, %1, %2, %3;" : "=l"(d) : "l"(a), "l"(b), "l"(d));
}
__device__ __forceinline__ float f2lo(u64 a) { return __uint_as_float((unsigned)a); }
__device__ __forceinline__ float f2hi(u64 a) { return __uint_as_float((unsigned)(a >> 32)); }

__device__ __forceinline__ float sigmoidf_(float x) {
    float e = __expf(-x);
    return __fdividef(1.f, 1.f + e);
}
__device__ __forceinline__ float tanhf_(float x) {
    float e = __expf(2.f * x);
    return 1.f - __fdividef(2.f, e + 1.f);
}

__global__ void __launch_bounds__(NTHREADS, 1)
seq2seq_kernel(const float* __restrict__ source,
               const float* __restrict__ eWih, const float* __restrict__ eWhh,
               const float* __restrict__ eBih, const float* __restrict__ eBhh,
               const float* __restrict__ dWih, const float* __restrict__ dWhh,
               const float* __restrict__ dBih, const float* __restrict__ dBhh,
               const float* __restrict__ fcW,  const float* __restrict__ fcB,
               float* __restrict__ out, int S, int T)
{
    extern __shared__ char smem_raw[];
    float4* wbuf = (float4*)smem_raw;                 // [K4N][4 types][JP]
    float4* hbuf = wbuf + K4N * 4 * JP;               // [2][K4N][BT]
    float*  xdec = (float*)(hbuf + 2 * HBUF_F4);      // [BT]
    float*  fcw  = xdec + BT;                         // [HID]
    float*  fcb  = fcw + HID;                         // [2]
    float*  srcsT = fcb + 2;                          // [S][BT] transposed!

    const int tid  = threadIdx.x;
    const int lane = tid & 31;
    const int wrp  = tid >> 5;                        // [0,16)
    const int b0g  = blockIdx.x * BT;

    // thread = (hidden unit j, batch pair); warp = 4 j x 8 pairs (all 16 b)
    const int jl = lane >> 3;                         // [0,4)
    const int bp = lane & 7;                          // [0,8)
    const int j  = wrp * 4 + jl;                      // [0,64)
    const int b0 = bp * 2;
    const int b1 = b0 + 1;

    // ---- stage weights: layout [k4][type][JP] float4 (4 k-values per float4)
    auto stage_w = [&](const float* Whh) {
        for (int idx = tid; idx < K4N * 4 * JP; idx += NTHREADS) {
            int k4 = idx / (4 * JP);
            int r  = idx % (4 * JP);
            int ty = r / JP, jj = r % JP;
            float4 v = make_float4(0.f, 0.f, 0.f, 0.f);
            if (jj < HID) {
                int row = ty * HID + jj;
                #pragma unroll
                for (int c = 0; c < 4; c++) {
                    int k = 4 * k4 + c;
                    if (k < HID) ((float*)&v)[c] = Whh[row * HID + k];
                }
            }
            wbuf[idx] = v;
        }
    };

    stage_w(eWhh);
    for (int i = tid; i < 2 * HBUF_F4; i += NTHREADS)
        hbuf[i] = make_float4(0.f, 0.f, 0.f, 0.f);
    if (tid < BT)  xdec[tid] = 0.f;
    if (tid < HID) fcw[tid] = fcW[tid];
    if (tid == 0)  fcb[0] = fcB[0];
    // transpose source slice: srcsT[t][b] (coalesced gmem read; one-time)
    for (int idx = tid; idx < BT * S; idx += NTHREADS) {
        int bl = idx / S, t = idx % S;
        srcsT[t * BT + bl] = source[(size_t)(b0g + bl) * S + t];
    }

    // ---- per-thread constants / state
    float biasr[4], wihr[4];
    auto stage_c = [&](const float* Wih, const float* Bih, const float* Bhh) {
        #pragma unroll
        for (int ty = 0; ty < 4; ty++) {
            if (j < HID) {
                int row = ty * HID + j;
                biasr[ty] = Bih[row] + Bhh[row];
                wihr[ty]  = Wih[row];
            } else { biasr[ty] = 0.f; wihr[ty] = 0.f; }
        }
    };
    stage_c(eWih, eBih, eBhh);
    float c0 = 0.f, c1 = 0.f;
    __syncthreads();

    const ulonglong2* w2 = (const ulonglong2*)wbuf;
    float g[8];  // [type][b-pair] gate pre-activations; index 2*ty+bi

    auto gemm = [&](const ulonglong2* hb2, float x0v, float x1v) {
        u64 a[8];
        #pragma unroll
        for (int ty = 0; ty < 4; ty++) {
            a[2 * ty]     = (u64)__float_as_uint(fmaf(x0v, wihr[ty], biasr[ty]));
            a[2 * ty + 1] = (u64)__float_as_uint(fmaf(x1v, wihr[ty], biasr[ty]));
        }
        #pragma unroll
        for (int k4 = 0; k4 < K4N; k4++) {
            ulonglong2 hv0 = hb2[k4 * BT + b0];   // 8 distinct 16B: dense 1 wf
            ulonglong2 hv1 = hb2[k4 * BT + b1];
            #pragma unroll
            for (int ty = 0; ty < 4; ty++) {
                ulonglong2 wv = w2[(k4 * 4 + ty) * JP + j];  // 4 distinct 16B: 1 wf
                ffma2(a[2 * ty],     wv.x, hv0.x);
                ffma2(a[2 * ty],     wv.y, hv0.y);
                ffma2(a[2 * ty + 1], wv.x, hv1.x);
                ffma2(a[2 * ty + 1], wv.y, hv1.y);
            }
        }
        #pragma unroll
        for (int i = 0; i < 8; i++) g[i] = f2lo(a[i]) + f2hi(a[i]);
    };

    // in-thread LSTM update: gates never leave registers
    auto update = [&](float* hnext) {
        {
            float iv = sigmoidf_(g[0]);
            float fv = sigmoidf_(g[2]);
            float gv = tanhf_(g[4]);
            float ov = sigmoidf_(g[6]);
            c0 = fmaf(fv, c0, iv * gv);
            float h = ov * tanhf_(c0);
            if (j < HID) hnext[(j >> 2) * (BT * 4) + b0 * 4 + (j & 3)] = h;
        }
        {
            float iv = sigmoidf_(g[1]);
            float fv = sigmoidf_(g[3]);
            float gv = tanhf_(g[5]);
            float ov = sigmoidf_(g[7]);
            c1 = fmaf(fv, c1, iv * gv);
            float h = ov * tanhf_(c1);
            if (j < HID) hnext[(j >> 2) * (BT * 4) + b1 * 4 + (j & 3)] = h;
        }
    };

    int pb = 0;

    // ================= encoder =================
    for (int t = 0; t < S; t++) {
        const ulonglong2* cur = (const ulonglong2*)(hbuf + pb * HBUF_F4);
        float* nxt = (float*)(hbuf + (pb ^ 1) * HBUF_F4);
        float x0v = srcsT[t * BT + b0];
        float x1v = srcsT[t * BT + b1];
        gemm(cur, x0v, x1v);
        update(nxt);
        pb ^= 1;
        __syncthreads();
    }

    // ================= swap to decoder weights =================
    stage_w(dWhh);
    stage_c(dWih, dBih, dBhh);
    __syncthreads();

    // ================= decoder =================
    for (int t = 0; t < T; t++) {
        const ulonglong2* cur = (const ulonglong2*)(hbuf + pb * HBUF_F4);
        float* nxt = (float*)(hbuf + (pb ^ 1) * HBUF_F4);
        float x0v = xdec[b0];
        float x1v = xdec[b1];
        gemm(cur, x0v, x1v);
        update(nxt);
        pb ^= 1;
        __syncthreads();                      // h_t visible

        if (wrp == 0) {                       // fc: y[b] = h . fcW + fcb
            const float* hf = (const float*)(hbuf + pb * HBUF_F4);
            const int bfc = lane & 15;
            const int hhf = lane >> 4;
            float s = 0.f;
            #pragma unroll
            for (int jj2 = 0; jj2 < 25; jj2++) {
                int jq = hhf * 25 + jj2;
                s = fmaf(hf[(jq >> 2) * (BT * 4) + bfc * 4 + (jq & 3)], fcw[jq], s);
            }
            s += __shfl_xor_sync(0xffffffffu, s, 16);
            if (hhf == 0) {
                float y = s + fcb[0];
                xdec[bfc] = y;
                out[(size_t)(b0g + bfc) * T + t] = y;
            }
        }
        __syncthreads();                      // xdec ready for next step
    }
}

extern "C" void kernel_launch(void* const* d_in, const int* in_sizes, int n_in,
                              void* d_out, int out_size)
{
    const float* source = (const float*)d_in[0];
    const float* eWih = (const float*)d_in[1];
    const float* eWhh = (const float*)d_in[2];
    const float* eBih = (const float*)d_in[3];
    const float* eBhh = (const float*)d_in[4];
    const float* dWih = (const float*)d_in[5];
    const float* dWhh = (const float*)d_in[6];
    const float* dBih = (const float*)d_in[7];
    const float* dBhh = (const float*)d_in[8];
    const float* fcW  = (const float*)d_in[9];
    const float* fcB  = (const float*)d_in[10];
    float* out = (float*)d_out;

    const int B = 2048;
    const int S = in_sizes[0] / B;   // 512
    const int T = out_size   / B;    // 256

    size_t sm = sizeof(float4) * (size_t)(K4N * 4 * JP + 2 * HBUF_F4)
              + sizeof(float)  * (size_t)(BT + HID + 2)
              + sizeof(float)  * (size_t)BT * S;

    cudaFuncSetAttribute(seq2seq_kernel, cudaFuncAttributeMaxDynamicSharedMemorySize, (int)sm);
    seq2seq_kernel<<<B / BT, NTHREADS, sm>>>(source, eWih, eWhh, eBih, eBhh,
                                             dWih, dWhh, dBih, dBhh, fcW, fcB,
                                             out, S, T);
}

// round 9
// speedup vs baseline: 1.5513x; 1.2403x over previous
#include <cuda_runtime.h>

#define HID 50
#define GP  224      // 4 types * 56 j-slots
#define NGG 32       // gate-groups of 7
#define K4N 13       // k padded 50->52, 4 per float4
#define BT  16
#define NTHREADS 512 // 16 warps

typedef unsigned long long u64;

__device__ __forceinline__ void ffma2(u64& d, u64 a, u64 b) {
    asm("fma.rn.f32x2 %0, %1, %2, %3;" : "=l"(d) : "l"(a), "l"(b), "l"(d));
}
__device__ __forceinline__ float f2lo(u64 a) { return __uint_as_float((unsigned)a); }
__device__ __forceinline__ float f2hi(u64 a) { return __uint_as_float((unsigned)(a >> 32)); }

__device__ __forceinline__ float sigmoidf_(float x) {
    float e = __expf(-x);
    return __fdividef(1.f, 1.f + e);
}
__device__ __forceinline__ float tanhf_(float x) {
    float e = __expf(2.f * x);
    return 1.f - __fdividef(2.f, e + 1.f);
}

__global__ void __launch_bounds__(NTHREADS, 1)
seq2seq_kernel(const float* __restrict__ source,
               const float* __restrict__ eWih, const float* __restrict__ eWhh,
               const float* __restrict__ eBih, const float* __restrict__ eBhh,
               const float* __restrict__ dWih, const float* __restrict__ dWhh,
               const float* __restrict__ dBih, const float* __restrict__ dBhh,
               const float* __restrict__ fcW,  const float* __restrict__ fcB,
               float* __restrict__ out, int S, int T)
{
    extern __shared__ char smem_raw[];
    float4* wenc  = (float4*)smem_raw;                // [(k4*7+i)*32 + gg]
    float4* wdec  = wenc + K4N * 7 * NGG;
    float4* h4    = wdec + K4N * 7 * NGG;             // [(k4*2+par)*8 + pos]
    float*  gatesf= (float*)(h4 + K4N * 2 * 8);       // [g(224)][16]
    float*  xdec  = gatesf + GP * BT;                 // [BT]
    float*  fcw   = xdec + BT;                        // [HID]
    float*  fcb   = fcw + HID;                        // [2]
    float*  srcsT = fcb + 2;                          // [S][BT]
    float*  h4f   = (float*)h4;

    const int tid  = threadIdx.x;
    const int lane = tid & 31;
    const int wrp  = tid >> 5;                        // [0,16)
    const int b0g  = blockIdx.x * BT;

    // GEMM tile: thread = (1 batch row, 7 gates). warp owns gg {2w, 2w+1}
    const int b    = lane >> 1;                       // [0,16): batch row
    const int ggl  = lane & 1;
    const int gg   = wrp * 2 + ggl;                   // [0,32)
    const int gbase= gg * 7;                          // [0,224)
    const int hpar = b & 1;                           // h4 parity/pos for this row
    const int hpos = b >> 1;

    // ---- stage weights, interleaved by gate-group: dst[(k4*7+i)*32 + gg]
    auto stage_w = [&](float4* dst, const float* Whh) {
        for (int idx = tid; idx < K4N * GP; idx += NTHREADS) {
            int k4 = idx / GP, g = idx % GP;
            int ggi = g / 7, ii = g % 7;
            int ty = g / 56, j = g % 56;
            float4 v = make_float4(0.f, 0.f, 0.f, 0.f);
            if (j < HID) {
                int row = ty * HID + j;
                #pragma unroll
                for (int c = 0; c < 4; c++) {
                    int k = 4 * k4 + c;
                    if (k < HID) ((float*)&v)[c] = Whh[row * HID + k];
                }
            }
            dst[(k4 * 7 + ii) * NGG + ggi] = v;
        }
    };
    stage_w(wenc, eWhh);
    stage_w(wdec, dWhh);
    for (int i = tid; i < K4N * 2 * 8; i += NTHREADS) h4[i] = make_float4(0.f, 0.f, 0.f, 0.f);
    if (tid < BT)  xdec[tid] = 0.f;
    if (tid < HID) fcw[tid] = fcW[tid];
    if (tid == 0)  fcb[0] = fcB[0];
    // transpose source slice (coalesced gmem reads)
    for (int idx = tid; idx < BT * S; idx += NTHREADS) {
        int bl = idx / S, t = idx % S;
        srcsT[t * BT + bl] = source[(size_t)(b0g + bl) * S + t];
    }

    // ---- per-thread constants / state
    float biasr[7], wihr[7];
    auto stage_c = [&](const float* Wih, const float* Bih, const float* Bhh) {
        #pragma unroll
        for (int i = 0; i < 7; i++) {
            int g = gbase + i, ty = g / 56, j = g % 56;
            if (j < HID) { int r = ty * HID + j; biasr[i] = Bih[r] + Bhh[r]; wihr[i] = Wih[r]; }
            else         { biasr[i] = 0.f; wihr[i] = 0.f; }
        }
    };
    stage_c(eWih, eBih, eBhh);

    // update role (r3 mapping): cell0 j<32 always; cell1 j in [32,50) for tid<288
    const int bu0 = tid & 15,         ju0 = tid >> 4;
    const int bu1 = (tid + 512) & 15, ju1 = (tid + 512) >> 4;
    const bool has1 = (tid + 512) < BT * HID;        // tid < 288
    float c0 = 0.f, c1 = 0.f;
    __syncthreads();

    const ulonglong2* h2 = (const ulonglong2*)h4;

    auto gemm = [&](const float4* wp, float xv) {
        u64 acc[7];
        #pragma unroll
        for (int i = 0; i < 7; i++)
            acc[i] = (u64)__float_as_uint(fmaf(xv, wihr[i], biasr[i]));
        const ulonglong2* w2 = (const ulonglong2*)wp;
        #pragma unroll
        for (int k4 = 0; k4 < K4N; k4++) {
            ulonglong2 hv = h2[(k4 * 2 + hpar) * 8 + hpos];   // 16 distinct f4, 2 dense lines
            #pragma unroll
            for (int i = 0; i < 7; i++) {
                ulonglong2 wv = w2[(k4 * 7 + i) * NGG + gg];  // 2 adjacent 16B: 1 wf
                ffma2(acc[i], wv.x, hv.x);
                ffma2(acc[i], wv.y, hv.y);
            }
        }
        #pragma unroll
        for (int i = 0; i < 7; i++) {
            u64 a = acc[i];
            gatesf[(gbase + i) * BT + b] = f2lo(a) + f2hi(a);  // bank-conflict-free
        }
    };

    auto upd_one = [&](int bb, int j, float& c) {
        float gi  = gatesf[(0 * 56 + j) * BT + bb];
        float gf  = gatesf[(1 * 56 + j) * BT + bb];
        float gg_ = gatesf[(2 * 56 + j) * BT + bb];
        float go  = gatesf[(3 * 56 + j) * BT + bb];
        float iv = sigmoidf_(gi);
        float fv = sigmoidf_(gf);
        float gv = tanhf_(gg_);
        float ov = sigmoidf_(go);
        c = fmaf(fv, c, iv * gv);
        float h = ov * tanhf_(c);
        h4f[((j >> 2) * 2 + (bb & 1)) * 32 + (bb >> 1) * 4 + (j & 3)] = h;
    };

    // ================= encoder =================
    for (int t = 0; t < S; t++) {
        gemm(wenc, srcsT[t * BT + b]);
        __syncthreads();
        upd_one(bu0, ju0, c0);
        if (has1) upd_one(bu1, ju1, c1);
        __syncthreads();
    }

    // ================= decoder =================
    stage_c(dWih, dBih, dBhh);
    for (int t = 0; t < T; t++) {
        gemm(wdec, xdec[b]);
        __syncthreads();
        upd_one(bu0, ju0, c0);
        if (has1) upd_one(bu1, ju1, c1);
        __syncthreads();

        if (wrp == 0) {   // fc: y[b] = h . fcW + fcb  (2 lanes per row)
            const int bfc = lane & 15;
            const int hhf = lane >> 4;
            float s = 0.f;
            #pragma unroll
            for (int jj = 0; jj < 25; jj++) {
                int jq = hhf * 25 + jj;
                s = fmaf(h4f[((jq >> 2) * 2 + (bfc & 1)) * 32 + (bfc >> 1) * 4 + (jq & 3)],
                         fcw[jq], s);
            }
            s += __shfl_xor_sync(0xffffffffu, s, 16);
            if (hhf == 0) {
                float y = s + fcb[0];
                xdec[bfc] = y;
                out[(size_t)(b0g + bfc) * T + t] = y;
            }
        }
        __syncthreads();
    }
}

extern "C" void kernel_launch(void* const* d_in, const int* in_sizes, int n_in,
                              void* d_out, int out_size)
{
    const float* source = (const float*)d_in[0];
    const float* eWih = (const float*)d_in[1];
    const float* eWhh = (const float*)d_in[2];
    const float* eBih = (const float*)d_in[3];
    const float* eBhh = (const float*)d_in[4];
    const float* dWih = (const float*)d_in[5];
    const float* dWhh = (const float*)d_in[6];
    const float* dBih = (const float*)d_in[7];
    const float* dBhh = (const float*)d_in[8];
    const float* fcW  = (const float*)d_in[9];
    const float* fcB  = (const float*)d_in[10];
    float* out = (float*)d_out;

    const int B = 2048;
    const int S = in_sizes[0] / B;   // 512
    const int T = out_size   / B;    // 256

    size_t sm = sizeof(float4) * (size_t)(K4N * 7 * NGG * 2 + K4N * 2 * 8)
              + sizeof(float)  * (size_t)(GP * BT + BT + HID + 2)
              + sizeof(float)  * (size_t)BT * S;

    cudaFuncSetAttribute(seq2seq_kernel, cudaFuncAttributeMaxDynamicSharedMemorySize, (int)sm);
    seq2seq_kernel<<<B / BT, NTHREADS, sm>>>(source, eWih, eWhh, eBih, eBhh,
                                             dWih, dWhh, dBih, dBhh, fcW, fcB,
                                             out, S, T);
}

// round 10
// speedup vs baseline: 1.6338x; 1.0532x over previous
#include <cuda_runtime.h>

#define HID 50
#define GP  224      // 4 types * 56 j-slots
#define NGG 32       // gate-groups of 7
#define K4N 13       // k padded 50->52, 4 per float4
#define BT  16
#define NTHREADS 512 // 16 warps

typedef unsigned long long u64;

__device__ __forceinline__ void ffma2(u64& d, u64 a, u64 b) {
    asm("fma.rn.f32x2 %0, %1, %2, %3;" : "=l"(d) : "l"(a), "l"(b), "l"(d));
}
__device__ __forceinline__ float f2lo(u64 a) { return __uint_as_float((unsigned)a); }
__device__ __forceinline__ float f2hi(u64 a) { return __uint_as_float((unsigned)(a >> 32)); }

// MUFU.TANH: 1 MUFU op, abs err ~5e-4
__device__ __forceinline__ float tanh_a(float x) {
    float r;
    asm("tanh.approx.f32 %0, %1;" : "=f"(r) : "f"(x));
    return r;
}
__device__ __forceinline__ float sigmoid_a(float x) {
    return fmaf(0.5f, tanh_a(0.5f * x), 0.5f);
}

__global__ void __launch_bounds__(NTHREADS, 1)
seq2seq_kernel(const float* __restrict__ source,
               const float* __restrict__ eWih, const float* __restrict__ eWhh,
               const float* __restrict__ eBih, const float* __restrict__ eBhh,
               const float* __restrict__ dWih, const float* __restrict__ dWhh,
               const float* __restrict__ dBih, const float* __restrict__ dBhh,
               const float* __restrict__ fcW,  const float* __restrict__ fcB,
               float* __restrict__ out, int S, int T)
{
    extern __shared__ char smem_raw[];
    float4* wenc  = (float4*)smem_raw;                // [(k4*7+i)*32 + gg]
    float4* wdec  = wenc + K4N * 7 * NGG;
    float4* h4    = wdec + K4N * 7 * NGG;             // [(k4*2+par)*8 + pos]
    float*  gatesf= (float*)(h4 + K4N * 2 * 8);       // [g(224)][16]
    float*  xdec  = gatesf + GP * BT;                 // [BT]
    float*  fcw   = xdec + BT;                        // [HID]
    float*  fcb   = fcw + HID;                        // [2]
    float*  srcsT = fcb + 2;                          // [S][BT]
    float*  h4f   = (float*)h4;

    const int tid  = threadIdx.x;
    const int lane = tid & 31;
    const int wrp  = tid >> 5;                        // [0,16)
    const int b0g  = blockIdx.x * BT;

    // GEMM tile: thread = (1 batch row, 7 gates). warp owns gg {2w, 2w+1}
    const int b    = lane >> 1;                       // [0,16): batch row
    const int ggl  = lane & 1;
    const int gg   = wrp * 2 + ggl;                   // [0,32)
    const int gbase= gg * 7;                          // [0,224)
    const int hpar = b & 1;
    const int hpos = b >> 1;

    // ---- stage weights, interleaved by gate-group
    auto stage_w = [&](float4* dst, const float* Whh) {
        for (int idx = tid; idx < K4N * GP; idx += NTHREADS) {
            int k4 = idx / GP, g = idx % GP;
            int ggi = g / 7, ii = g % 7;
            int ty = g / 56, j = g % 56;
            float4 v = make_float4(0.f, 0.f, 0.f, 0.f);
            if (j < HID) {
                int row = ty * HID + j;
                #pragma unroll
                for (int c = 0; c < 4; c++) {
                    int k = 4 * k4 + c;
                    if (k < HID) ((float*)&v)[c] = Whh[row * HID + k];
                }
            }
            dst[(k4 * 7 + ii) * NGG + ggi] = v;
        }
    };
    stage_w(wenc, eWhh);
    stage_w(wdec, dWhh);
    for (int i = tid; i < K4N * 2 * 8; i += NTHREADS) h4[i] = make_float4(0.f, 0.f, 0.f, 0.f);
    if (tid < BT)  xdec[tid] = 0.f;
    if (tid < HID) fcw[tid] = fcW[tid];
    if (tid == 0)  fcb[0] = fcB[0];
    for (int idx = tid; idx < BT * S; idx += NTHREADS) {
        int bl = idx / S, t = idx % S;
        srcsT[t * BT + bl] = source[(size_t)(b0g + bl) * S + t];
    }

    // ---- per-thread constants / state
    float biasr[7], wihr[7];
    auto stage_c = [&](const float* Wih, const float* Bih, const float* Bhh) {
        #pragma unroll
        for (int i = 0; i < 7; i++) {
            int g = gbase + i, ty = g / 56, j = g % 56;
            if (j < HID) { int r = ty * HID + j; biasr[i] = Bih[r] + Bhh[r]; wihr[i] = Wih[r]; }
            else         { biasr[i] = 0.f; wihr[i] = 0.f; }
        }
    };
    stage_c(eWih, eBih, eBhh);

    // update role: cell0 j<32 always; cell1 j in [32,50) for tid<288
    const int bu0 = tid & 15,         ju0 = tid >> 4;
    const int bu1 = (tid + 512) & 15, ju1 = (tid + 512) >> 4;
    const bool has1 = (tid + 512) < BT * HID;        // tid < 288
    float c0 = 0.f, c1 = 0.f;
    __syncthreads();

    const ulonglong2* h2 = (const ulonglong2*)h4;

    auto gemm = [&](const float4* wp, float xv) {
        u64 acc[7];
        #pragma unroll
        for (int i = 0; i < 7; i++)
            acc[i] = (u64)__float_as_uint(fmaf(xv, wihr[i], biasr[i]));
        const ulonglong2* w2 = (const ulonglong2*)wp;
        #pragma unroll
        for (int k4 = 0; k4 < K4N; k4++) {
            ulonglong2 hv = h2[(k4 * 2 + hpar) * 8 + hpos];
            #pragma unroll
            for (int i = 0; i < 7; i++) {
                ulonglong2 wv = w2[(k4 * 7 + i) * NGG + gg];
                ffma2(acc[i], wv.x, hv.x);
                ffma2(acc[i], wv.y, hv.y);
            }
        }
        #pragma unroll
        for (int i = 0; i < 7; i++) {
            u64 a = acc[i];
            gatesf[(gbase + i) * BT + b] = f2lo(a) + f2hi(a);
        }
    };

    auto upd_one = [&](int bb, int j, float& c) {
        float gi  = gatesf[(0 * 56 + j) * BT + bb];
        float gf  = gatesf[(1 * 56 + j) * BT + bb];
        float gg_ = gatesf[(2 * 56 + j) * BT + bb];
        float go  = gatesf[(3 * 56 + j) * BT + bb];
        float iv = sigmoid_a(gi);
        float fv = sigmoid_a(gf);
        float gv = tanh_a(gg_);
        float ov = sigmoid_a(go);
        c = fmaf(fv, c, iv * gv);
        float h = ov * tanh_a(c);
        h4f[((j >> 2) * 2 + (bb & 1)) * 32 + (bb >> 1) * 4 + (j & 3)] = h;
    };

    // ================= encoder =================
    for (int t = 0; t < S; t++) {
        gemm(wenc, srcsT[t * BT + b]);
        __syncthreads();
        upd_one(bu0, ju0, c0);
        if (has1) upd_one(bu1, ju1, c1);
        __syncthreads();
    }

    // ================= decoder =================
    stage_c(dWih, dBih, dBhh);
    for (int t = 0; t < T; t++) {
        gemm(wdec, xdec[b]);
        __syncthreads();
        upd_one(bu0, ju0, c0);
        if (has1) upd_one(bu1, ju1, c1);
        __syncthreads();

        if (wrp == 0) {   // fc: y[b] = h . fcW + fcb  (2 lanes per row)
            const int bfc = lane & 15;
            const int hhf = lane >> 4;
            float s = 0.f;
            #pragma unroll
            for (int jj = 0; jj < 25; jj++) {
                int jq = hhf * 25 + jj;
                s = fmaf(h4f[((jq >> 2) * 2 + (bfc & 1)) * 32 + (bfc >> 1) * 4 + (jq & 3)],
                         fcw[jq], s);
            }
            s += __shfl_xor_sync(0xffffffffu, s, 16);
            if (hhf == 0) {
                float y = s + fcb[0];
                xdec[bfc] = y;
                out[(size_t)(b0g + bfc) * T + t] = y;
            }
        }
        __syncthreads();
    }
}

extern "C" void kernel_launch(void* const* d_in, const int* in_sizes, int n_in,
                              void* d_out, int out_size)
{
    const float* source = (const float*)d_in[0];
    const float* eWih = (const float*)d_in[1];
    const float* eWhh = (const float*)d_in[2];
    const float* eBih = (const float*)d_in[3];
    const float* eBhh = (const float*)d_in[4];
    const float* dWih = (const float*)d_in[5];
    const float* dWhh = (const float*)d_in[6];
    const float* dBih = (const float*)d_in[7];
    const float* dBhh = (const float*)d_in[8];
    const float* fcW  = (const float*)d_in[9];
    const float* fcB  = (const float*)d_in[10];
    float* out = (float*)d_out;

    const int B = 2048;
    const int S = in_sizes[0] / B;   // 512
    const int T = out_size   / B;    // 256

    size_t sm = sizeof(float4) * (size_t)(K4N * 7 * NGG * 2 + K4N * 2 * 8)
              + sizeof(float)  * (size_t)(GP * BT + BT + HID + 2)
              + sizeof(float)  * (size_t)BT * S;

    cudaFuncSetAttribute(seq2seq_kernel, cudaFuncAttributeMaxDynamicSharedMemorySize, (int)sm);
    seq2seq_kernel<<<B / BT, NTHREADS, sm>>>(source, eWih, eWhh, eBih, eBhh,
                                             dWih, dWhh, dBih, dBhh, fcW, fcB,
                                             out, S, T);
}